// round 13
// baseline (speedup 1.0000x reference)
#include <cuda_runtime.h>
#include <math.h>

#define NT    4096
#define SEQ   128
#define DIN   32
#define DLAT  64
#define NU    256
#define INDIM 160
#define TM    32
#define NTH   512

typedef unsigned long long u64;
typedef ulonglong2 u64x2;

// ---------- packed f32x2 helpers ----------
__device__ __forceinline__ u64 bcast2(float a) {
    u64 r; asm("mov.b64 %0, {%1, %1};" : "=l"(r) : "f"(a)); return r;
}
__device__ __forceinline__ u64 pk2(float x, float y) {
    u64 r; asm("mov.b64 %0, {%1, %2};" : "=l"(r) : "f"(x), "f"(y)); return r;
}
__device__ __forceinline__ float2 unpk(u64 v) {
    float2 f; asm("mov.b64 {%0, %1}, %2;" : "=f"(f.x), "=f"(f.y) : "l"(v)); return f;
}
__device__ __forceinline__ void fma2(u64& d, u64 a, u64 b) {
    asm("fma.rn.f32x2 %0, %1, %2, %0;" : "+l"(d) : "l"(a), "l"(b));
}
__device__ __forceinline__ u64 mul2(u64 a, u64 b) {
    u64 d; asm("mul.rn.f32x2 %0, %1, %2;" : "=l"(d) : "l"(a), "l"(b)); return d;
}
__device__ __forceinline__ float tanh_f(float x) {
    return 1.0f - __fdividef(2.0f, __expf(2.0f * x) + 1.0f);
}
__device__ __forceinline__ float sigmoid_f(float x) {
    return __fdividef(1.0f, 1.0f + __expf(-x));
}

// ---------- cp.async helpers ----------
__device__ __forceinline__ void cpa16(unsigned d, const float* s) {
    asm volatile("cp.async.cg.shared.global [%0], [%1], 16;" :: "r"(d), "l"(s));
}
#define CPCOMMIT() asm volatile("cp.async.commit_group;")
#define CPWAIT1()  asm volatile("cp.async.wait_group 1;")
#define CPWAIT0()  asm volatile("cp.async.wait_group 0;")

// 16KB slab, one source (512 threads x 32B)
__device__ __forceinline__ void copy16(float* dst, const float* __restrict__ src, int tid) {
    unsigned d = (unsigned)__cvta_generic_to_shared(dst) + tid * 16;
    cpa16(d,        src + tid * 4);
    cpa16(d + 8192, src + tid * 4 + 2048);
}
// 8KB + 8KB, two sources
__device__ __forceinline__ void copy8x2(float* dst, const float* __restrict__ sa,
                                        const float* __restrict__ sb, int tid) {
    unsigned d = (unsigned)__cvta_generic_to_shared(dst) + tid * 16;
    cpa16(d,        sa + tid * 4);
    cpa16(d + 8192, sb + tid * 4);
}

__device__ __forceinline__ int nxt1(int c) { return (c == 2) ? 0 : c + 1; }
__device__ __forceinline__ int nxt2(int c) { return (c == 0) ? 2 : c - 1; }

// Layouts:
//  dup buffers  (yT, ycT, ccT): [feature k][64] with row r duplicated at 2r, 2r+1
//  plain buffers (lvT, uT, h1A, h1B): [feature k][32], row r at k*32+r
struct Smem {
    float wbuf[3][4096];   // 3 x 16KB weight slabs
    float yT [DLAT * 64];
    float ycT[INDIM * 64];
    float ccT[INDIM * 64];
    float lvT[DLAT * 32];
    float uT [DLAT * 32];
    float h1A[NU * 32];
    float h1B[NU * 32];
    float ts[SEQ];
};

// ---------- first layer slab (N=256): zero-MOV, W read once per SM ----------
// thread: rows 2p,2p+1 x cols c0..c0+7. acc[row e][col-pair g] = {d(.,c0+2g), d(.,c0+2g+1)}
template<int SK>
__device__ __forceinline__ void fl_slab(const float* __restrict__ Ad,
                                        const float* __restrict__ Ws,
                                        int kbase, u64 acc[2][4], int c0, int p4)
{
    const float* Ap = Ad + kbase * 64 + p4;
    const float* Wp = Ws + c0;
#pragma unroll 4
    for (int kk = 0; kk < SK; ++kk) {
        u64x2 a   = *reinterpret_cast<const u64x2*>(Ap + kk * 64);   // {a0,a0},{a1,a1}
        u64x2 w01 = *reinterpret_cast<const u64x2*>(Wp + kk * 256);  // {wc0,wc1},{wc2,wc3}
        u64x2 w23 = *reinterpret_cast<const u64x2*>(Wp + kk * 256 + 4);
        fma2(acc[0][0], a.x, w01.x); fma2(acc[0][1], a.x, w01.y);
        fma2(acc[0][2], a.x, w23.x); fma2(acc[0][3], a.x, w23.y);
        fma2(acc[1][0], a.y, w01.x); fma2(acc[1][1], a.y, w01.y);
        fma2(acc[1][2], a.y, w23.x); fma2(acc[1][3], a.y, w23.y);
    }
}

template<int SK>
__device__ __forceinline__ void fl_slab_dual(const float* __restrict__ Ad,
                                             const float* __restrict__ Wsu,
                                             const float* __restrict__ Wsr,
                                             int kbase, u64 aU[2][4], u64 aR[2][4],
                                             int c0, int p4)
{
    const float* Ap = Ad + kbase * 64 + p4;
    const float* Wu = Wsu + c0;
    const float* Wr = Wsr + c0;
#pragma unroll 4
    for (int kk = 0; kk < SK; ++kk) {
        u64x2 a = *reinterpret_cast<const u64x2*>(Ap + kk * 64);
        u64x2 u01 = *reinterpret_cast<const u64x2*>(Wu + kk * 256);
        u64x2 u23 = *reinterpret_cast<const u64x2*>(Wu + kk * 256 + 4);
        u64x2 r01 = *reinterpret_cast<const u64x2*>(Wr + kk * 256);
        u64x2 r23 = *reinterpret_cast<const u64x2*>(Wr + kk * 256 + 4);
        fma2(aU[0][0], a.x, u01.x); fma2(aU[0][1], a.x, u01.y);
        fma2(aU[0][2], a.x, u23.x); fma2(aU[0][3], a.x, u23.y);
        fma2(aU[1][0], a.y, u01.x); fma2(aU[1][1], a.y, u01.y);
        fma2(aU[1][2], a.y, u23.x); fma2(aU[1][3], a.y, u23.y);
        fma2(aR[0][0], a.x, r01.x); fma2(aR[0][1], a.x, r01.y);
        fma2(aR[0][2], a.x, r23.x); fma2(aR[0][3], a.x, r23.y);
        fma2(aR[1][0], a.y, r01.x); fma2(aR[1][1], a.y, r01.y);
        fma2(aR[1][2], a.y, r23.x); fma2(aR[1][3], a.y, r23.y);
    }
}

// first-layer epilogue: tanh + repack cols->row-pairs into h1 [k][32]
__device__ __forceinline__ void fl_epi(u64 acc[2][4], const float* __restrict__ bias,
                                       float* __restrict__ OT, int c0, int p2)
{
    float4 bA = *reinterpret_cast<const float4*>(bias + c0);
    float4 bB = *reinterpret_cast<const float4*>(bias + c0 + 4);
    float bb[8] = {bA.x, bA.y, bA.z, bA.w, bB.x, bB.y, bB.z, bB.w};
#pragma unroll
    for (int g = 0; g < 4; ++g) {
        float2 r0 = unpk(acc[0][g]);
        float2 r1 = unpk(acc[1][g]);
        int c = c0 + 2 * g;
        *reinterpret_cast<u64*>(OT + c * 32 + p2) =
            pk2(tanh_f(r0.x + bb[2 * g]), tanh_f(r1.x + bb[2 * g]));
        *reinterpret_cast<u64*>(OT + (c + 1) * 32 + p2) =
            pk2(tanh_f(r0.y + bb[2 * g + 1]), tanh_f(r1.y + bb[2 * g + 1]));
    }
}

// ---------- second layer slab (N=64): A broadcast from h1 [k][32] ----------
// thread: cols 2c2,2c2+1, rows 2pr,2pr+1. Ah pre-offset by kbase*32 + 2*pr.
template<int SR>
__device__ __forceinline__ void sl_slab(const float* __restrict__ Ah,
                                        const float* __restrict__ Ws,
                                        int c2x2, u64& a0, u64& a1)
{
#pragma unroll 8
    for (int kk = 0; kk < SR; ++kk) {
        u64 a = *reinterpret_cast<const u64*>(Ah + kk * 32);
        float2 w = *reinterpret_cast<const float2*>(Ws + kk * 64 + c2x2);
        fma2(a0, a, bcast2(w.x));
        fma2(a1, a, bcast2(w.y));
    }
}

template<int SR>
__device__ __forceinline__ void sl_slab_dual(const float* __restrict__ Au,
                                             const float* __restrict__ Ar,
                                             const float* __restrict__ Wsu,
                                             const float* __restrict__ Wsr,
                                             int c2x2,
                                             u64& u0, u64& u1, u64& r0, u64& r1)
{
#pragma unroll 8
    for (int kk = 0; kk < SR; ++kk) {
        u64 au = *reinterpret_cast<const u64*>(Au + kk * 32);
        u64 ar = *reinterpret_cast<const u64*>(Ar + kk * 32);
        float2 wu = *reinterpret_cast<const float2*>(Wsu + kk * 64 + c2x2);
        float2 wr = *reinterpret_cast<const float2*>(Wsr + kk * 64 + c2x2);
        fma2(u0, au, bcast2(wu.x));
        fma2(u1, au, bcast2(wu.y));
        fma2(r0, ar, bcast2(wr.x));
        fma2(r1, ar, bcast2(wr.y));
    }
}

// candidate layer 2 (N=128): low cols 2c2.. and high cols 64+2c2..
template<int SR>
__device__ __forceinline__ void f_slab(const float* __restrict__ Ah,
                                       const float* __restrict__ Ws,
                                       int c2x2, u64 aS[2], u64 aD[2])
{
#pragma unroll 8
    for (int kk = 0; kk < SR; ++kk) {
        u64 a = *reinterpret_cast<const u64*>(Ah + kk * 32);
        float2 wl = *reinterpret_cast<const float2*>(Ws + kk * 128 + c2x2);
        float2 wh = *reinterpret_cast<const float2*>(Ws + kk * 128 + 64 + c2x2);
        fma2(aS[0], a, bcast2(wl.x));
        fma2(aS[1], a, bcast2(wl.y));
        fma2(aD[0], a, bcast2(wh.x));
        fma2(aD[1], a, bcast2(wh.y));
    }
}

__global__ __launch_bounds__(NTH, 1)
void ode_rnn_kernel(const float* __restrict__ data,
                    const float* __restrict__ tsteps,
                    const float* __restrict__ Wo1, const float* __restrict__ bo1,
                    const float* __restrict__ Wo2, const float* __restrict__ bo2,
                    const float* __restrict__ Wu1, const float* __restrict__ bu1,
                    const float* __restrict__ Wu2, const float* __restrict__ bu2,
                    const float* __restrict__ Wr1, const float* __restrict__ br1,
                    const float* __restrict__ Wr2, const float* __restrict__ br2,
                    const float* __restrict__ Wn1, const float* __restrict__ bn1,
                    const float* __restrict__ Wn2, const float* __restrict__ bn2,
                    float* __restrict__ out)
{
    extern __shared__ float smem_raw[];
    Smem* S = reinterpret_cast<Smem*>(smem_raw);
    const int tid = threadIdx.x;
    const int traj0 = blockIdx.x * TM;

    const int lane = tid & 31;
    const int wid  = tid >> 5;          // 0..15
    const int p    = lane & 15;         // first-layer row-pair
    const int h    = lane >> 4;         // first-layer col half
    const int c0   = wid * 16 + h * 8;  // first-layer col base (8 cols)
    const int p4   = 4 * p;             // dup-A byte offset (floats)
    const int p2   = 2 * p;             // h1 store offset

    const int c2   = lane;              // second-layer col-pair (cols 2c2, 2c2+1)
    const int prw  = wid;               // second-layer row-pair
    const int q4   = 4 * prw;           // dup offset for second-layer rows
    const int q2   = 2 * prw;

    for (int i = tid; i < DLAT * 64; i += NTH) S->yT[i] = 0.f;
    for (int i = tid; i < DLAT * 32; i += NTH) S->lvT[i] = 0.f;
    for (int i = tid; i < SEQ; i += NTH) S->ts[i] = tsteps[i];

    // prologue: first two slabs of Wo1
    copy16(S->wbuf[0], Wo1, tid);        CPCOMMIT();
    copy16(S->wbuf[1], Wo1 + 4096, tid); CPCOMMIT();
    int cb = 0;
    __syncthreads();

    for (int s = 0; s < SEQ - 1; ++s) {
        const float dt = (s == 0) ? (S->ts[1] - S->ts[0]) : (S->ts[s] - S->ts[s + 1]);

        // x prefetch; lv -> ycT dup cols [64:128)  (same-thread RAW vs prev F epilogue)
        float xv[2];
#pragma unroll
        for (int e = 0; e < 2; ++e) {
            int idx = tid + e * NTH;               // 0..1023
            int r = idx >> 5, c = idx & 31;
            xv[e] = data[(size_t)(traj0 + r) * SEQ * DIN + (size_t)(s + 1) * DIN + c];
        }
#pragma unroll
        for (int j = 0; j < 2; ++j) {
            int c = 2 * c2 + j;
            float2 l = unpk(*reinterpret_cast<const u64*>(S->lvT + c * 32 + q2));
            *reinterpret_cast<u64*>(S->ycT + (DLAT + c) * 64 + q4)     = bcast2(l.x);
            *reinterpret_cast<u64*>(S->ycT + (DLAT + c) * 64 + q4 + 2) = bcast2(l.y);
        }

        // ===== Phase A: ODE L1 (4 slabs x 16k) =====
        u64 aA[2][4];
#pragma unroll
        for (int g = 0; g < 4; ++g) { aA[0][g] = 0; aA[1][g] = 0; }
#pragma unroll 1
        for (int i = 0; i < 4; ++i) {
            CPWAIT1(); __syncthreads();
            if (i < 2) copy16(S->wbuf[nxt2(cb)], Wo1 + (i + 2) * 4096, tid);
            else       copy16(S->wbuf[nxt2(cb)], Wo2 + (i - 2) * 4096, tid);
            CPCOMMIT();
            fl_slab<16>(S->yT, S->wbuf[cb], 16 * i, aA, c0, p4);
            if (i == 3) {
                fl_epi(aA, bo1, S->h1A, c0, p2);
#pragma unroll
                for (int e = 0; e < 2; ++e) {     // stage x -> ycT/ccT dup cols [128:160)
                    int idx = tid + e * NTH;
                    int r = idx >> 5, c = idx & 31;
                    u64 xd = bcast2(xv[e]);
                    *reinterpret_cast<u64*>(S->ycT + (2 * DLAT + c) * 64 + 2 * r) = xd;
                    *reinterpret_cast<u64*>(S->ccT + (2 * DLAT + c) * 64 + 2 * r) = xd;
                }
            }
            cb = nxt1(cb);
        }

        // ===== Phase B: ODE L2 (4 slabs x 64k) =====
        u64 b0 = 0, b1 = 0;
#pragma unroll 1
        for (int i = 0; i < 4; ++i) {
            CPWAIT1(); __syncthreads();
            if (i < 2) copy16(S->wbuf[nxt2(cb)], Wo2 + (i + 2) * 4096, tid);
            else       copy8x2(S->wbuf[nxt2(cb)], Wu1 + (i - 2) * 2048, Wr1 + (i - 2) * 2048, tid);
            CPCOMMIT();
            sl_slab<64>(S->h1A + (64 * i) * 32 + q2, S->wbuf[cb], 2 * c2, b0, b1);
            if (i == 3) {   // epilogue: ycT dup cols [0:64) = y + (o+b)*dt
                float2 bb = *reinterpret_cast<const float2*>(bo2 + 2 * c2);
                float bj[2] = {bb.x, bb.y};
                u64 accs[2] = {b0, b1};
#pragma unroll
                for (int j = 0; j < 2; ++j) {
                    int c = 2 * c2 + j;
                    float2 o = unpk(accs[j]);
                    u64x2 yd = *reinterpret_cast<const u64x2*>(S->yT + c * 64 + q4);
                    float rx = fmaf(o.x + bj[j], dt, unpk(yd.x).x);
                    float ry = fmaf(o.y + bj[j], dt, unpk(yd.y).x);
                    *reinterpret_cast<u64*>(S->ycT + c * 64 + q4)     = bcast2(rx);
                    *reinterpret_cast<u64*>(S->ycT + c * 64 + q4 + 2) = bcast2(ry);
                }
            }
            cb = nxt1(cb);
        }

        // ===== Phase C: update+reset L1 (20 dual slabs x 8k) =====
        u64 aU[2][4], aR[2][4];
#pragma unroll
        for (int g = 0; g < 4; ++g) { aU[0][g]=0; aU[1][g]=0; aR[0][g]=0; aR[1][g]=0; }
#pragma unroll 1
        for (int ci = 0; ci < 20; ++ci) {
            CPWAIT1(); __syncthreads();
            if (ci < 18) copy8x2(S->wbuf[nxt2(cb)], Wu1 + (ci + 2) * 2048, Wr1 + (ci + 2) * 2048, tid);
            else         copy8x2(S->wbuf[nxt2(cb)], Wu2 + (ci - 18) * 2048, Wr2 + (ci - 18) * 2048, tid);
            CPCOMMIT();
            fl_slab_dual<8>(S->ycT, S->wbuf[cb], S->wbuf[cb] + 2048, 8 * ci, aU, aR, c0, p4);
            if (ci == 19) {
                fl_epi(aU, bu1, S->h1A, c0, p2);
                fl_epi(aR, br1, S->h1B, c0, p2);
            }
            cb = nxt1(cb);
        }

        // ===== Phase D: update+reset L2 (8 dual slabs x 32k) =====
        u64 dU0 = 0, dU1 = 0, dR0 = 0, dR1 = 0;
#pragma unroll 1
        for (int di = 0; di < 8; ++di) {
            CPWAIT1(); __syncthreads();
            if (di < 6) copy8x2(S->wbuf[nxt2(cb)], Wu2 + (di + 2) * 2048, Wr2 + (di + 2) * 2048, tid);
            else        copy16(S->wbuf[nxt2(cb)], Wn1 + (di - 6) * 4096, tid);
            CPCOMMIT();
            sl_slab_dual<32>(S->h1A + (32 * di) * 32 + q2, S->h1B + (32 * di) * 32 + q2,
                             S->wbuf[cb], S->wbuf[cb] + 2048, 2 * c2, dU0, dU1, dR0, dR1);
            if (di == 7) {   // epilogue -> uT, ccT dup cols [0:128)
                float2 bu = *reinterpret_cast<const float2*>(bu2 + 2 * c2);
                float2 br = *reinterpret_cast<const float2*>(br2 + 2 * c2);
                float buj[2] = {bu.x, bu.y};
                float brj[2] = {br.x, br.y};
                u64 accU[2] = {dU0, dU1};
                u64 accR[2] = {dR0, dR1};
#pragma unroll
                for (int j = 0; j < 2; ++j) {
                    int c = 2 * c2 + j;
                    float2 vu = unpk(accU[j]);
                    *reinterpret_cast<u64*>(S->uT + c * 32 + q2) =
                        pk2(sigmoid_f(vu.x + buj[j]), sigmoid_f(vu.y + buj[j]));
                    float2 vr = unpk(accR[j]);
                    u64 r0d = bcast2(sigmoid_f(vr.x + brj[j]));
                    u64 r1d = bcast2(sigmoid_f(vr.y + brj[j]));
                    u64x2 ylo = *reinterpret_cast<const u64x2*>(S->ycT + c * 64 + q4);
                    u64x2 yhi = *reinterpret_cast<const u64x2*>(S->ycT + (c + DLAT) * 64 + q4);
                    *reinterpret_cast<u64*>(S->ccT + c * 64 + q4)              = mul2(ylo.x, r0d);
                    *reinterpret_cast<u64*>(S->ccT + c * 64 + q4 + 2)          = mul2(ylo.y, r1d);
                    *reinterpret_cast<u64*>(S->ccT + (c + DLAT) * 64 + q4)     = mul2(yhi.x, r0d);
                    *reinterpret_cast<u64*>(S->ccT + (c + DLAT) * 64 + q4 + 2) = mul2(yhi.y, r1d);
                }
            }
            cb = nxt1(cb);
        }

        // ===== Phase E: candidate L1 (10 slabs x 16k) =====
        u64 aE[2][4];
#pragma unroll
        for (int g = 0; g < 4; ++g) { aE[0][g] = 0; aE[1][g] = 0; }
#pragma unroll 1
        for (int ei = 0; ei < 10; ++ei) {
            CPWAIT1(); __syncthreads();
            if (ei < 8) copy16(S->wbuf[nxt2(cb)], Wn1 + (ei + 2) * 4096, tid);
            else        copy16(S->wbuf[nxt2(cb)], Wn2 + (ei - 8) * 4096, tid);
            CPCOMMIT();
            fl_slab<16>(S->ccT, S->wbuf[cb], 16 * ei, aE, c0, p4);
            if (ei == 9) fl_epi(aE, bn1, S->h1A, c0, p2);
            cb = nxt1(cb);
        }

        // ===== Phase F: candidate L2 (8 slabs x 32k) + fused state update =====
        u64 fS[2] = {0, 0}, fD[2] = {0, 0};
#pragma unroll 1
        for (int fi = 0; fi < 8; ++fi) {
            CPWAIT1(); __syncthreads();
            if (fi < 6) copy16(S->wbuf[nxt2(cb)], Wn2 + (fi + 2) * 4096, tid);
            else        copy16(S->wbuf[nxt2(cb)], Wo1 + (fi - 6) * 4096, tid);  // next-step A
            CPCOMMIT();
            f_slab<32>(S->h1A + (32 * fi) * 32 + q2, S->wbuf[cb], 2 * c2, fS, fD);
            if (fi == 7) {
                float2 bl = *reinterpret_cast<const float2*>(bn2 + 2 * c2);
                float2 bh = *reinterpret_cast<const float2*>(bn2 + DLAT + 2 * c2);
                float blj[2] = {bl.x, bl.y};
                float bhj[2] = {bh.x, bh.y};
#pragma unroll
                for (int j = 0; j < 2; ++j) {
                    int c = 2 * c2 + j;
                    float2 ns = unpk(fS[j]);
                    ns.x += blj[j]; ns.y += blj[j];
                    float2 nd = unpk(fD[j]);
                    nd.x = fabsf(nd.x + bhj[j]); nd.y = fabsf(nd.y + bhj[j]);
                    float2 uu = unpk(*reinterpret_cast<const u64*>(S->uT + c * 32 + q2));
                    u64x2 yod = *reinterpret_cast<const u64x2*>(S->ycT + c * 64 + q4);
                    float yo0 = unpk(yod.x).x, yo1 = unpk(yod.y).x;
                    float2 lo = unpk(*reinterpret_cast<const u64*>(S->lvT + c * 32 + q2));
                    float ny0 = (1.f - uu.x) * ns.x + uu.x * yo0;
                    float ny1 = (1.f - uu.y) * ns.y + uu.y * yo1;
                    float nl0 = (1.f - uu.x) * nd.x + uu.x * lo.x;
                    float nl1 = (1.f - uu.y) * nd.y + uu.y * lo.y;
                    *reinterpret_cast<u64*>(S->yT + c * 64 + q4)     = bcast2(ny0);
                    *reinterpret_cast<u64*>(S->yT + c * 64 + q4 + 2) = bcast2(ny1);
                    *reinterpret_cast<u64*>(S->lvT + c * 32 + q2) = pk2(nl0, nl1);
                }
            }
            cb = nxt1(cb);
        }
    }

    CPWAIT0(); __syncthreads();

    // ===== output: yi (4096x64) then yi_logvar (4096x64) =====
    for (int i = tid; i < TM * DLAT; i += NTH) {
        int r = i >> 6, c = i & 63;
        out[(size_t)(traj0 + r) * DLAT + c] = S->yT[c * 64 + 2 * r];
        out[(size_t)NT * DLAT + (size_t)(traj0 + r) * DLAT + c] = S->lvT[c * 32 + r];
    }
}

extern "C" void kernel_launch(void* const* d_in, const int* in_sizes, int n_in,
                              void* d_out, int out_size) {
    const float* data = (const float*)d_in[0];
    const float* ts   = (const float*)d_in[1];
    const float* Wo1  = (const float*)d_in[2];
    const float* bo1  = (const float*)d_in[3];
    const float* Wo2  = (const float*)d_in[4];
    const float* bo2  = (const float*)d_in[5];
    const float* Wu1  = (const float*)d_in[6];
    const float* bu1  = (const float*)d_in[7];
    const float* Wu2  = (const float*)d_in[8];
    const float* bu2  = (const float*)d_in[9];
    const float* Wr1  = (const float*)d_in[10];
    const float* br1  = (const float*)d_in[11];
    const float* Wr2  = (const float*)d_in[12];
    const float* br2  = (const float*)d_in[13];
    const float* Wn1  = (const float*)d_in[14];
    const float* bn1  = (const float*)d_in[15];
    const float* Wn2  = (const float*)d_in[16];
    const float* bn2  = (const float*)d_in[17];
    float* out = (float*)d_out;

    const int smem = (int)sizeof(Smem);
    cudaFuncSetAttribute(ode_rnn_kernel,
                         cudaFuncAttributeMaxDynamicSharedMemorySize, smem);
    ode_rnn_kernel<<<NT / TM, NTH, smem>>>(
        data, ts, Wo1, bo1, Wo2, bo2, Wu1, bu1, Wu2, bu2,
        Wr1, br1, Wr2, br2, Wn1, bn1, Wn2, bn2, out);
}

// round 14
// speedup vs baseline: 1.4609x; 1.4609x over previous
#include <cuda_runtime.h>
#include <math.h>

#define NT    4096
#define SEQ   128
#define DIN   32
#define DLAT  64
#define NU    256
#define INDIM 160
#define TM    16
#define NTH   128

typedef unsigned long long u64;

// ---------- packed f32x2 helpers ----------
__device__ __forceinline__ u64 bcast2(float a) {
    u64 r; asm("mov.b64 %0, {%1, %1};" : "=l"(r) : "f"(a)); return r;
}
__device__ __forceinline__ u64 pk2(float x, float y) {
    u64 r; asm("mov.b64 %0, {%1, %2};" : "=l"(r) : "f"(x), "f"(y)); return r;
}
__device__ __forceinline__ float2 unpk(u64 v) {
    float2 f; asm("mov.b64 {%0, %1}, %2;" : "=f"(f.x), "=f"(f.y) : "l"(v)); return f;
}
__device__ __forceinline__ void fma2(u64& d, u64 a, u64 b) {
    asm("fma.rn.f32x2 %0, %1, %2, %0;" : "+l"(d) : "l"(a), "l"(b));
}
__device__ __forceinline__ u64 mul2(u64 a, u64 b) {
    u64 d; asm("mul.rn.f32x2 %0, %1, %2;" : "=l"(d) : "l"(a), "l"(b)); return d;
}
__device__ __forceinline__ float tanh_f(float x) {
    return 1.0f - __fdividef(2.0f, __expf(2.0f * x) + 1.0f);
}
__device__ __forceinline__ float sigmoid_f(float x) {
    return __fdividef(1.0f, 1.0f + __expf(-x));
}

// ---------- cp.async helpers ----------
__device__ __forceinline__ void cpa16(unsigned d, const float* s) {
    asm volatile("cp.async.cg.shared.global [%0], [%1], 16;" :: "r"(d), "l"(s));
}
#define CPCOMMIT() asm volatile("cp.async.commit_group;")
#define CPWAIT1()  asm volatile("cp.async.wait_group 1;")
#define CPWAIT0()  asm volatile("cp.async.wait_group 0;")

// 16KB slab, one source (128 threads x 128B)
__device__ __forceinline__ void copy16(float* dst, const float* __restrict__ src, int tid) {
    unsigned d = (unsigned)__cvta_generic_to_shared(dst) + tid * 16;
#pragma unroll
    for (int i = 0; i < 8; ++i) cpa16(d + i * 2048, src + tid * 4 + i * 512);
}
// 8KB + 8KB, two sources
__device__ __forceinline__ void copy8x2(float* dst, const float* __restrict__ sa,
                                        const float* __restrict__ sb, int tid) {
    unsigned d = (unsigned)__cvta_generic_to_shared(dst) + tid * 16;
#pragma unroll
    for (int i = 0; i < 4; ++i) cpa16(d + i * 2048, sa + tid * 4 + i * 512);
#pragma unroll
    for (int i = 0; i < 4; ++i) cpa16(d + 8192 + i * 2048, sb + tid * 4 + i * 512);
}

__device__ __forceinline__ int nxt1(int c) { return (c == 2) ? 0 : c + 1; }
__device__ __forceinline__ int nxt2(int c) { return (c == 0) ? 2 : c - 1; }

// ---------- smem layouts (8 row-pairs for TM=16) ----------
#define XI(c, p)  ((p)*128 + (((c)&1)*32 + ((c)>>1))*2)     // 64-col buffers
#define YI(c, p)  ((p)*320 + (((c)&1)*80 + ((c)>>1))*2)     // 160-col buffers
// 256-col hidden: pair block 512 floats, col c -> slot (c&3)*64 + (c>>2)

struct Smem {
    float wbuf[3][4096];   // 3 x 16KB weight slabs
    float yT [8 * 128];
    float lvT[8 * 128];
    float uT [8 * 128];
    float ycT[8 * 320];
    float ccT[8 * 320];
    float h1A[8 * 512];
    float h1B[8 * 512];
    float ts[SEQ];
};   // 112.5 KB -> two CTAs fit in the 228KB carveout

// ---------- first-layer slab: acc += A^T W over SK rows (broadcast A) ----------
template<int COLS, int SK>
__device__ __forceinline__ void fl_slab(const float* __restrict__ AT,
                                        const float* __restrict__ Ws,
                                        int k0, u64 acc[4][4], int cg, int rg)
{
    const float4* W4 = reinterpret_cast<const float4*>(Ws) + cg;
    const float* Ap = AT + (4 * rg) * (2 * COLS);
#pragma unroll 4
    for (int kk = 0; kk < SK; ++kk) {
        const int k = k0 + kk;
        float4 w = W4[kk * 64];
        u64 w0 = bcast2(w.x), w1 = bcast2(w.y), w2 = bcast2(w.z), w3 = bcast2(w.w);
        const int m = ((k & 1) * (COLS / 2) + (k >> 1)) * 2;
#pragma unroll
        for (int q = 0; q < 4; ++q) {
            u64 a = *reinterpret_cast<const u64*>(Ap + q * (2 * COLS) + m);
            fma2(acc[q][0], a, w0); fma2(acc[q][1], a, w1);
            fma2(acc[q][2], a, w2); fma2(acc[q][3], a, w3);
        }
    }
}

template<int COLS, int SK>
__device__ __forceinline__ void fl_slab_dual(const float* __restrict__ AT,
                                             const float* __restrict__ Wsu,
                                             const float* __restrict__ Wsr,
                                             int k0, u64 aU[4][4], u64 aR[4][4],
                                             int cg, int rg)
{
    const float4* WU = reinterpret_cast<const float4*>(Wsu) + cg;
    const float4* WR = reinterpret_cast<const float4*>(Wsr) + cg;
    const float* Ap = AT + (4 * rg) * (2 * COLS);
#pragma unroll 4
    for (int kk = 0; kk < SK; ++kk) {
        const int k = k0 + kk;
        float4 wu = WU[kk * 64];
        float4 wr = WR[kk * 64];
        u64 u0 = bcast2(wu.x), u1 = bcast2(wu.y), u2 = bcast2(wu.z), u3 = bcast2(wu.w);
        u64 r0 = bcast2(wr.x), r1 = bcast2(wr.y), r2 = bcast2(wr.z), r3 = bcast2(wr.w);
        const int m = ((k & 1) * (COLS / 2) + (k >> 1)) * 2;
#pragma unroll
        for (int q = 0; q < 4; ++q) {
            u64 a = *reinterpret_cast<const u64*>(Ap + q * (2 * COLS) + m);
            fma2(aU[q][0], a, u0); fma2(aU[q][1], a, u1);
            fma2(aU[q][2], a, u2); fma2(aU[q][3], a, u3);
            fma2(aR[q][0], a, r0); fma2(aR[q][1], a, r1);
            fma2(aR[q][2], a, r2); fma2(aR[q][3], a, r3);
        }
    }
}

// first-layer epilogue: tanh + store into h1 layout [pair][slot]
__device__ __forceinline__ void fl_epi(u64 acc[4][4], const float* __restrict__ bias,
                                       float* __restrict__ OT, int cg, int rg)
{
    float4 b4 = reinterpret_cast<const float4*>(bias)[cg];
    float bb[4] = {b4.x, b4.y, b4.z, b4.w};
#pragma unroll
    for (int q = 0; q < 4; ++q)
#pragma unroll
        for (int j = 0; j < 4; ++j) {
            float2 v = unpk(acc[q][j]);
            v.x = tanh_f(v.x + bb[j]);
            v.y = tanh_f(v.y + bb[j]);
            *reinterpret_cast<u64*>(OT + (4 * rg + q) * 512 + (j * 64 + cg) * 2) = pk2(v.x, v.y);
        }
}

// ---------- second-layer slab (N=64): SR k-rows, 2 pairs x 2 cols ----------
template<int SR>
__device__ __forceinline__ void sl_slab(const float* __restrict__ A0,
                                        const float* __restrict__ A1,
                                        const float* __restrict__ Ws,
                                        int k0, int cp, u64 acc[2][2])
{
    const float2* W2 = reinterpret_cast<const float2*>(Ws) + cp;
#pragma unroll 4
    for (int kk = 0; kk < SR; ++kk) {
        const int k = k0 + kk;
        const int o = ((k & 3) * 64 + (k >> 2)) * 2;
        u64 a0 = *reinterpret_cast<const u64*>(A0 + o);
        u64 a1 = *reinterpret_cast<const u64*>(A1 + o);
        float2 w = W2[kk * 32];
        u64 wx = bcast2(w.x), wy = bcast2(w.y);
        fma2(acc[0][0], a0, wx); fma2(acc[0][1], a0, wy);
        fma2(acc[1][0], a1, wx); fma2(acc[1][1], a1, wy);
    }
}

template<int SR>
__device__ __forceinline__ void sl_slab_dual(const float* __restrict__ Aa0,
                                             const float* __restrict__ Aa1,
                                             const float* __restrict__ Ab0,
                                             const float* __restrict__ Ab1,
                                             const float* __restrict__ Wsu,
                                             const float* __restrict__ Wsr,
                                             int k0, int cp,
                                             u64 aU[2][2], u64 aR[2][2])
{
    const float2* WU = reinterpret_cast<const float2*>(Wsu) + cp;
    const float2* WR = reinterpret_cast<const float2*>(Wsr) + cp;
#pragma unroll 4
    for (int kk = 0; kk < SR; ++kk) {
        const int k = k0 + kk;
        const int o = ((k & 3) * 64 + (k >> 2)) * 2;
        u64 pa0 = *reinterpret_cast<const u64*>(Aa0 + o);
        u64 pa1 = *reinterpret_cast<const u64*>(Aa1 + o);
        u64 pb0 = *reinterpret_cast<const u64*>(Ab0 + o);
        u64 pb1 = *reinterpret_cast<const u64*>(Ab1 + o);
        float2 wu = WU[kk * 32];
        float2 wr = WR[kk * 32];
        u64 ux = bcast2(wu.x), uy = bcast2(wu.y);
        u64 rx = bcast2(wr.x), ry = bcast2(wr.y);
        fma2(aU[0][0], pa0, ux); fma2(aU[0][1], pa0, uy);
        fma2(aU[1][0], pa1, ux); fma2(aU[1][1], pa1, uy);
        fma2(aR[0][0], pb0, rx); fma2(aR[0][1], pb0, ry);
        fma2(aR[1][0], pb1, rx); fma2(aR[1][1], pb1, ry);
    }
}

// candidate layer 2 (N=128): low and high col groups
template<int SR>
__device__ __forceinline__ void f_slab(const float* __restrict__ A0,
                                       const float* __restrict__ A1,
                                       const float* __restrict__ Ws,
                                       int k0, int cp, u64 aS[2][2], u64 aD[2][2])
{
    const float2* W2 = reinterpret_cast<const float2*>(Ws);
#pragma unroll 4
    for (int kk = 0; kk < SR; ++kk) {
        const int k = k0 + kk;
        const int o = ((k & 3) * 64 + (k >> 2)) * 2;
        u64 a0 = *reinterpret_cast<const u64*>(A0 + o);
        u64 a1 = *reinterpret_cast<const u64*>(A1 + o);
        float2 wl = W2[kk * 64 + cp];
        float2 wh = W2[kk * 64 + 32 + cp];
        u64 wlx = bcast2(wl.x), wly = bcast2(wl.y);
        u64 whx = bcast2(wh.x), why = bcast2(wh.y);
        fma2(aS[0][0], a0, wlx); fma2(aS[0][1], a0, wly);
        fma2(aS[1][0], a1, wlx); fma2(aS[1][1], a1, wly);
        fma2(aD[0][0], a0, whx); fma2(aD[0][1], a0, why);
        fma2(aD[1][0], a1, whx); fma2(aD[1][1], a1, why);
    }
}

__global__ __launch_bounds__(NTH, 2)
void ode_rnn_kernel(const float* __restrict__ data,
                    const float* __restrict__ tsteps,
                    const float* __restrict__ Wo1, const float* __restrict__ bo1,
                    const float* __restrict__ Wo2, const float* __restrict__ bo2,
                    const float* __restrict__ Wu1, const float* __restrict__ bu1,
                    const float* __restrict__ Wu2, const float* __restrict__ bu2,
                    const float* __restrict__ Wr1, const float* __restrict__ br1,
                    const float* __restrict__ Wr2, const float* __restrict__ br2,
                    const float* __restrict__ Wn1, const float* __restrict__ bn1,
                    const float* __restrict__ Wn2, const float* __restrict__ bn2,
                    float* __restrict__ out)
{
    extern __shared__ float smem_raw[];
    Smem* S = reinterpret_cast<Smem*>(smem_raw);
    const int tid = threadIdx.x;
    const int traj0 = blockIdx.x * TM;

    const int cg  = tid & 63;          // first-layer cols 4cg..4cg+3
    const int rg  = tid >> 6;          // 0..1: pairs 4rg..4rg+3
    const int cp  = tid & 31;          // second-layer col-pair
    const int rp0 = (tid >> 5) * 2;    // second-layer pairs rp0, rp0+1 (0,2,4,6)

    for (int i = tid; i < 8 * 128; i += NTH) { S->yT[i] = 0.f; S->lvT[i] = 0.f; }
    for (int i = tid; i < SEQ; i += NTH) S->ts[i] = tsteps[i];

    // prologue: slabs A0, A1 of step 0
    copy16(S->wbuf[0], Wo1, tid);        CPCOMMIT();
    copy16(S->wbuf[1], Wo1 + 4096, tid); CPCOMMIT();
    int cb = 0;
    __syncthreads();

    const float* A0 = S->h1A + rp0 * 512;
    const float* A1 = A0 + 512;
    const float* B0 = S->h1B + rp0 * 512;
    const float* B1 = B0 + 512;

    for (int s = 0; s < SEQ - 1; ++s) {
        const float dt = (s == 0) ? (S->ts[1] - S->ts[0]) : (S->ts[s] - S->ts[s + 1]);

        // x prefetch (global); lv -> ycT[64:128) (same-thread RAW vs prev F epilogue)
        float xv[4];
#pragma unroll
        for (int e = 0; e < 4; ++e) {
            int idx = tid + e * NTH;               // 0..511
            int r = idx >> 5, c = idx & 31;
            xv[e] = data[(size_t)(traj0 + r) * SEQ * DIN + (size_t)(s + 1) * DIN + c];
        }
#pragma unroll
        for (int p = 0; p < 2; ++p)
#pragma unroll
            for (int j = 0; j < 2; ++j) {
                int c = 2 * cp + j, pr = rp0 + p;
                u64 v = *reinterpret_cast<const u64*>(S->lvT + XI(c, pr));
                *reinterpret_cast<u64*>(S->ycT + YI(c + DLAT, pr)) = v;
            }

        // ===== Phase A: ODE L1 (4 slabs x 16 rows) =====
        u64 aA[4][4];
#pragma unroll
        for (int q = 0; q < 4; ++q) { aA[q][0]=0; aA[q][1]=0; aA[q][2]=0; aA[q][3]=0; }
#pragma unroll 1
        for (int i = 0; i < 4; ++i) {
            CPWAIT1(); __syncthreads();
            if (i < 2) copy16(S->wbuf[nxt2(cb)], Wo1 + (i + 2) * 4096, tid);
            else       copy16(S->wbuf[nxt2(cb)], Wo2 + (i - 2) * 4096, tid);
            CPCOMMIT();
            fl_slab<DLAT, 16>(S->yT, S->wbuf[cb], 16 * i, aA, cg, rg);
            if (i == 3) {
                fl_epi(aA, bo1, S->h1A, cg, rg);
#pragma unroll
                for (int e = 0; e < 4; ++e) {     // stage x -> ycT/ccT[128:160)
                    int idx = tid + e * NTH;
                    int r = idx >> 5, c = idx & 31;
                    int a = YI(2 * DLAT + c, r >> 1) + (r & 1);
                    S->ycT[a] = xv[e];
                    S->ccT[a] = xv[e];
                }
            }
            cb = nxt1(cb);
        }

        // ===== Phase B: ODE L2 (4 slabs x 64 rows) =====
        u64 aB[2][2];
        aB[0][0]=0; aB[0][1]=0; aB[1][0]=0; aB[1][1]=0;
#pragma unroll 1
        for (int i = 0; i < 4; ++i) {
            CPWAIT1(); __syncthreads();
            if (i < 2) copy16(S->wbuf[nxt2(cb)], Wo2 + (i + 2) * 4096, tid);
            else       copy8x2(S->wbuf[nxt2(cb)], Wu1 + (i - 2) * 2048, Wr1 + (i - 2) * 2048, tid);
            CPCOMMIT();
            sl_slab<64>(A0, A1, S->wbuf[cb], 64 * i, cp, aB);
            if (i == 3) {   // epilogue: ycT[0:64) = y + (o+b)*dt
                float2 bb = *reinterpret_cast<const float2*>(bo2 + 2 * cp);
                float bj[2] = {bb.x, bb.y};
#pragma unroll
                for (int p = 0; p < 2; ++p)
#pragma unroll
                    for (int j = 0; j < 2; ++j) {
                        int c = 2 * cp + j, pr = rp0 + p;
                        float2 o = unpk(aB[p][j]);
                        float2 y = unpk(*reinterpret_cast<const u64*>(S->yT + XI(c, pr)));
                        float rx = fmaf(o.x + bj[j], dt, y.x);
                        float ry = fmaf(o.y + bj[j], dt, y.y);
                        *reinterpret_cast<u64*>(S->ycT + YI(c, pr)) = pk2(rx, ry);
                    }
            }
            cb = nxt1(cb);
        }

        // ===== Phase C: update+reset L1 (20 dual slabs x 8 rows) =====
        u64 aU4[4][4], aR4[4][4];
#pragma unroll
        for (int q = 0; q < 4; ++q)
#pragma unroll
            for (int j = 0; j < 4; ++j) { aU4[q][j] = 0; aR4[q][j] = 0; }
#pragma unroll 1
        for (int ci = 0; ci < 20; ++ci) {
            CPWAIT1(); __syncthreads();
            if (ci < 18) copy8x2(S->wbuf[nxt2(cb)], Wu1 + (ci + 2) * 2048, Wr1 + (ci + 2) * 2048, tid);
            else         copy8x2(S->wbuf[nxt2(cb)], Wu2 + (ci - 18) * 2048, Wr2 + (ci - 18) * 2048, tid);
            CPCOMMIT();
            fl_slab_dual<INDIM, 8>(S->ycT, S->wbuf[cb], S->wbuf[cb] + 2048, 8 * ci, aU4, aR4, cg, rg);
            if (ci == 19) {
                fl_epi(aU4, bu1, S->h1A, cg, rg);
                fl_epi(aR4, br1, S->h1B, cg, rg);
            }
            cb = nxt1(cb);
        }

        // ===== Phase D: update+reset L2 (8 dual slabs x 32 rows) =====
        u64 dU[2][2], dR[2][2];
        dU[0][0]=0; dU[0][1]=0; dU[1][0]=0; dU[1][1]=0;
        dR[0][0]=0; dR[0][1]=0; dR[1][0]=0; dR[1][1]=0;
#pragma unroll 1
        for (int di = 0; di < 8; ++di) {
            CPWAIT1(); __syncthreads();
            if (di < 6) copy8x2(S->wbuf[nxt2(cb)], Wu2 + (di + 2) * 2048, Wr2 + (di + 2) * 2048, tid);
            else        copy16(S->wbuf[nxt2(cb)], Wn1 + (di - 6) * 4096, tid);
            CPCOMMIT();
            sl_slab_dual<32>(A0, A1, B0, B1, S->wbuf[cb], S->wbuf[cb] + 2048, 32 * di, cp, dU, dR);
            if (di == 7) {   // epilogue -> uT, ccT[0:128)
                float2 bu = *reinterpret_cast<const float2*>(bu2 + 2 * cp);
                float2 br = *reinterpret_cast<const float2*>(br2 + 2 * cp);
                float buj[2] = {bu.x, bu.y};
                float brj[2] = {br.x, br.y};
#pragma unroll
                for (int p = 0; p < 2; ++p)
#pragma unroll
                    for (int j = 0; j < 2; ++j) {
                        int c = 2 * cp + j, pr = rp0 + p;
                        float2 vu = unpk(dU[p][j]);
                        *reinterpret_cast<u64*>(S->uT + XI(c, pr)) =
                            pk2(sigmoid_f(vu.x + buj[j]), sigmoid_f(vu.y + buj[j]));
                        float2 vr = unpk(dR[p][j]);
                        u64 rpair = pk2(sigmoid_f(vr.x + brj[j]), sigmoid_f(vr.y + brj[j]));
                        u64 ylo = *reinterpret_cast<const u64*>(S->ycT + YI(c, pr));
                        u64 yhi = *reinterpret_cast<const u64*>(S->ycT + YI(c + DLAT, pr));
                        *reinterpret_cast<u64*>(S->ccT + YI(c, pr))        = mul2(ylo, rpair);
                        *reinterpret_cast<u64*>(S->ccT + YI(c + DLAT, pr)) = mul2(yhi, rpair);
                    }
            }
            cb = nxt1(cb);
        }

        // ===== Phase E: candidate L1 (10 slabs x 16 rows) =====
        u64 aE[4][4];
#pragma unroll
        for (int q = 0; q < 4; ++q) { aE[q][0]=0; aE[q][1]=0; aE[q][2]=0; aE[q][3]=0; }
#pragma unroll 1
        for (int ei = 0; ei < 10; ++ei) {
            CPWAIT1(); __syncthreads();
            if (ei < 8) copy16(S->wbuf[nxt2(cb)], Wn1 + (ei + 2) * 4096, tid);
            else        copy16(S->wbuf[nxt2(cb)], Wn2 + (ei - 8) * 4096, tid);
            CPCOMMIT();
            fl_slab<INDIM, 16>(S->ccT, S->wbuf[cb], 16 * ei, aE, cg, rg);
            if (ei == 9) fl_epi(aE, bn1, S->h1A, cg, rg);
            cb = nxt1(cb);
        }

        // ===== Phase F: candidate L2 (8 slabs x 32 rows) + fused state update =====
        u64 fS[2][2], fD[2][2];
        fS[0][0]=0; fS[0][1]=0; fS[1][0]=0; fS[1][1]=0;
        fD[0][0]=0; fD[0][1]=0; fD[1][0]=0; fD[1][1]=0;
#pragma unroll 1
        for (int fi = 0; fi < 8; ++fi) {
            CPWAIT1(); __syncthreads();
            if (fi < 6) copy16(S->wbuf[nxt2(cb)], Wn2 + (fi + 2) * 4096, tid);
            else        copy16(S->wbuf[nxt2(cb)], Wo1 + (fi - 6) * 4096, tid);  // next-step A
            CPCOMMIT();
            f_slab<32>(A0, A1, S->wbuf[cb], 32 * fi, cp, fS, fD);
            if (fi == 7) {
                float2 bl = *reinterpret_cast<const float2*>(bn2 + 2 * cp);
                float2 bh = *reinterpret_cast<const float2*>(bn2 + DLAT + 2 * cp);
                float blj[2] = {bl.x, bl.y};
                float bhj[2] = {bh.x, bh.y};
#pragma unroll
                for (int p = 0; p < 2; ++p)
#pragma unroll
                    for (int j = 0; j < 2; ++j) {
                        int c = 2 * cp + j, pr = rp0 + p;
                        float2 ns = unpk(fS[p][j]);
                        ns.x += blj[j]; ns.y += blj[j];
                        float2 nd = unpk(fD[p][j]);
                        nd.x = fabsf(nd.x + bhj[j]); nd.y = fabsf(nd.y + bhj[j]);
                        float2 uu = unpk(*reinterpret_cast<const u64*>(S->uT + XI(c, pr)));
                        float2 yo = unpk(*reinterpret_cast<const u64*>(S->ycT + YI(c, pr)));
                        float2 lo = unpk(*reinterpret_cast<const u64*>(S->lvT + XI(c, pr)));
                        float ny0 = (1.f - uu.x) * ns.x + uu.x * yo.x;
                        float ny1 = (1.f - uu.y) * ns.y + uu.y * yo.y;
                        float nl0 = (1.f - uu.x) * nd.x + uu.x * lo.x;
                        float nl1 = (1.f - uu.y) * nd.y + uu.y * lo.y;
                        *reinterpret_cast<u64*>(S->yT + XI(c, pr))  = pk2(ny0, ny1);
                        *reinterpret_cast<u64*>(S->lvT + XI(c, pr)) = pk2(nl0, nl1);
                    }
            }
            cb = nxt1(cb);
        }
    }

    CPWAIT0(); __syncthreads();

    // ===== output: yi (4096x64) then yi_logvar (4096x64) =====
    for (int i = tid; i < TM * DLAT; i += NTH) {
        int r = i >> 6, c = i & 63;
        int a = XI(c, r >> 1) + (r & 1);
        out[(size_t)(traj0 + r) * DLAT + c] = S->yT[a];
        out[(size_t)NT * DLAT + (size_t)(traj0 + r) * DLAT + c] = S->lvT[a];
    }
}

extern "C" void kernel_launch(void* const* d_in, const int* in_sizes, int n_in,
                              void* d_out, int out_size) {
    const float* data = (const float*)d_in[0];
    const float* ts   = (const float*)d_in[1];
    const float* Wo1  = (const float*)d_in[2];
    const float* bo1  = (const float*)d_in[3];
    const float* Wo2  = (const float*)d_in[4];
    const float* bo2  = (const float*)d_in[5];
    const float* Wu1  = (const float*)d_in[6];
    const float* bu1  = (const float*)d_in[7];
    const float* Wu2  = (const float*)d_in[8];
    const float* bu2  = (const float*)d_in[9];
    const float* Wr1  = (const float*)d_in[10];
    const float* br1  = (const float*)d_in[11];
    const float* Wr2  = (const float*)d_in[12];
    const float* br2  = (const float*)d_in[13];
    const float* Wn1  = (const float*)d_in[14];
    const float* bn1  = (const float*)d_in[15];
    const float* Wn2  = (const float*)d_in[16];
    const float* bn2  = (const float*)d_in[17];
    float* out = (float*)d_out;

    const int smem = (int)sizeof(Smem);
    cudaFuncSetAttribute(ode_rnn_kernel,
                         cudaFuncAttributeMaxDynamicSharedMemorySize, smem);
    ode_rnn_kernel<<<NT / TM, NTH, smem>>>(
        data, ts, Wo1, bo1, Wo2, bo2, Wu1, bu1, Wu2, bu2,
        Wr1, br1, Wr2, br2, Wn1, bn1, Wn2, bn2, out);
}